// round 16
// baseline (speedup 1.0000x reference)
#include <cuda_runtime.h>
#include <cuda_fp16.h>
#include <cstdint>

#define DM 1024
#define H 16
#define BATCH 4
#define SEQ 8192
#define MTOT (BATCH*SEQ)

// ---- standard GEMM: CTA 128x128, warp 32x64, 3 stages ----
#define BM 128
#define BN 128
#define BK 64
#define NCH (DM/BK)
#define LDS_ 72
#define TB (128*LDS_*2)
#define STAGE_B (2*TB)
#define DYN (3*STAGE_B)         // 110592 -> 2 CTAs/SM
#define NTHR 256

// ---- S GEMM ----
#define S_LDSE 136
#define S_TB (64*S_LDSE*2)
#define S_STAGE (2*S_TB)
#define S_NCH (SEQ/64)

// ---- T GEMM ----
#define T_STAGE (3*TB)
#define T_DYN (2*T_STAGE)       // 110592

#define CS_SEG 32
#define KV_SEG 8

// grid split constants
#define N_PROJ 2048
#define N_S    256
#define N_CS   512
#define COMBO_GRID (N_PROJ + N_S + N_CS)
#define N_T    256
#define N_MV   1024
#define TCOMBO_GRID (N_T + N_MV)
#define N_CI   (2*((MTOT*DM/4)/256))   // 65536 (keys, values only)
#define N_CW   (2*((DM*DM/4)/256))     // 2048
#define N_ZC   ((2*BATCH*DM)/256)      // 32
#define N_ZKV  ((BATCH*H*64*64)/256)   // 1024
#define CONV_GRID (N_CI + N_CW + N_ZC + N_ZKV)

// ---------------- scratch ----------------------------------------------------
__device__ __half g_in[2][(size_t)MTOT*DM];                   // keys, values fp16
__device__ __half g_w[2][DM*DM];                              // Wq, Wk fp16
__device__ __half g_qn[(size_t)MTOT*DM];
__device__ __half g_w2[(size_t)BATCH*DM*DM];
__device__ __half g_sth[BATCH][DM*DM];
__device__ __half g_stl[BATCH][DM*DM];
__device__ float  g_T[(size_t)BATCH*DM*DM];
__device__ float  g_kv[BATCH*H*64*64];
__device__ float  g_cs[2][BATCH][DM];
__device__ float  g_uv[2][BATCH][DM];

// ---------------- helpers ------------------------------------------------------
static __device__ __forceinline__ uint32_t s2u(const void* p){
    uint32_t r;
    asm("{ .reg .u64 t; cvta.to.shared.u64 t, %1; cvt.u32.u64 %0, t; }" : "=r"(r) : "l"(p));
    return r;
}
static __device__ __forceinline__ void cp16(uint32_t dst, const void* src){
    asm volatile("cp.async.cg.shared.global [%0], [%1], 16;" :: "r"(dst), "l"(src));
}
#define CP_COMMIT() asm volatile("cp.async.commit_group;" ::: "memory")
#define LDM4(r, a) asm volatile( \
    "ldmatrix.sync.aligned.m8n8.x4.shared.b16 {%0,%1,%2,%3}, [%4];" \
    : "=r"((r)[0]),"=r"((r)[1]),"=r"((r)[2]),"=r"((r)[3]) : "r"(a))
#define LDM4T(r, a) asm volatile( \
    "ldmatrix.sync.aligned.m8n8.x4.trans.shared.b16 {%0,%1,%2,%3}, [%4];" \
    : "=r"((r)[0]),"=r"((r)[1]),"=r"((r)[2]),"=r"((r)[3]) : "r"(a))
#define MMA(d, a, b0_, b1_) asm volatile( \
    "mma.sync.aligned.m16n8k16.row.col.f32.f16.f16.f32 " \
    "{%0,%1,%2,%3},{%4,%5,%6,%7},{%8,%9},{%0,%1,%2,%3};" \
    : "+f"((d)[0]),"+f"((d)[1]),"+f"((d)[2]),"+f"((d)[3]) \
    : "r"((a)[0]),"r"((a)[1]),"r"((a)[2]),"r"((a)[3]), "r"(b0_),"r"(b1_))

// ---------------- fp16 GEMM core (3-stage, single sync) ------------------------
// AF32=1: A operand loaded from fp32 source with in-register fp16 convert.
template<int EPI, int AF32>
static __device__ __forceinline__ void gemm_core(
    const __half* __restrict__ Ah, const float* __restrict__ Af32,
    const __half* __restrict__ Bh,
    const float* __restrict__ bias, const float* __restrict__ gamma,
    float* __restrict__ C, __half* __restrict__ Oh, int bm, int bn)
{
    extern __shared__ __half smbuf[];
    const uint32_t smu = s2u(smbuf);
    const int tid = threadIdx.x, lane = tid & 31, wid = tid >> 5;
    const int wm = wid & 3, wn = wid >> 2;

    const uint32_t a_off = (uint32_t)((wm*32 + (lane & 15))*LDS_ + (lane >> 4)*8)*2;
    const uint32_t b_off = (uint32_t)TB +
                           (uint32_t)((wn*64 + (lane & 15))*LDS_ + (lane >> 4)*8)*2;

    float acc[2][8][4];
#pragma unroll
    for (int i = 0; i < 2; i++)
#pragma unroll
        for (int j = 0; j < 8; j++)
#pragma unroll
            for (int q = 0; q < 4; q++) acc[i][j][q] = 0.f;

#define ISSUE(c_) do {                                                         \
        const int c__ = (c_);                                                  \
        const uint32_t sb = smu + (uint32_t)((c__ % 3) * STAGE_B);             \
        const int k0 = c__ * BK;                                               \
        if (AF32){                                                             \
            _Pragma("unroll")                                                  \
            for (int it = 0; it < 4; it++){                                    \
                int id = tid + it*NTHR;                                        \
                int r = id >> 3, cg = id & 7;                                  \
                const float* src = Af32 + (size_t)(bm + r)*DM + k0 + cg*8;     \
                float4 x0 = *reinterpret_cast<const float4*>(src);             \
                float4 x1 = *reinterpret_cast<const float4*>(src + 4);         \
                __half2 p0 = __floats2half2_rn(x0.x, x0.y);                    \
                __half2 p1 = __floats2half2_rn(x0.z, x0.w);                    \
                __half2 p2 = __floats2half2_rn(x1.x, x1.y);                    \
                __half2 p3 = __floats2half2_rn(x1.z, x1.w);                    \
                uint32_t ad = sb + (uint32_t)(r*LDS_ + cg*8)*2;                \
                asm volatile("st.shared.v4.b32 [%0], {%1,%2,%3,%4};"           \
                    :: "r"(ad),                                                \
                       "r"(*reinterpret_cast<uint32_t*>(&p0)),                 \
                       "r"(*reinterpret_cast<uint32_t*>(&p1)),                 \
                       "r"(*reinterpret_cast<uint32_t*>(&p2)),                 \
                       "r"(*reinterpret_cast<uint32_t*>(&p3)));                \
            }                                                                  \
        } else {                                                               \
            _Pragma("unroll")                                                  \
            for (int it = 0; it < 4; it++){                                    \
                int id = tid + it*NTHR;                                        \
                int r = id >> 3, cg = id & 7;                                  \
                cp16(sb + (uint32_t)(r*LDS_ + cg*8)*2,                         \
                     Ah + (size_t)(bm + r)*DM + k0 + cg*8);                    \
            }                                                                  \
        }                                                                      \
        _Pragma("unroll")                                                      \
        for (int it = 0; it < 4; it++){                                        \
            int id = tid + it*NTHR;                                            \
            int r = id >> 3, cg = id & 7;                                      \
            cp16(sb + (uint32_t)TB + (uint32_t)(r*LDS_ + cg*8)*2,              \
                 Bh + (size_t)(bn + r)*DM + k0 + cg*8);                        \
        }                                                                      \
        CP_COMMIT();                                                           \
    } while(0)

    ISSUE(0); ISSUE(1);
    for (int c = 0; c < NCH; c++){
        if (c + 1 < NCH) asm volatile("cp.async.wait_group 1;" ::: "memory");
        else             asm volatile("cp.async.wait_group 0;" ::: "memory");
        __syncthreads();
        if (c + 2 < NCH) ISSUE(c + 2);

        const uint32_t sb = smu + (uint32_t)((c % 3) * STAGE_B);
#pragma unroll
        for (int ks = 0; ks < 4; ks++){
            uint32_t bf[4][4];
#pragma unroll
            for (int np = 0; np < 4; np++)
                LDM4(bf[np], sb + b_off + (uint32_t)(np*16*LDS_ + ks*16)*2);
#pragma unroll
            for (int mt = 0; mt < 2; mt++){
                uint32_t af[4];
                LDM4(af, sb + a_off + (uint32_t)(mt*16*LDS_ + ks*16)*2);
#pragma unroll
                for (int nt = 0; nt < 8; nt++){
                    const int np = nt >> 1, sub = nt & 1;
                    MMA(acc[mt][nt], af, bf[np][sub], bf[np][sub+2]);
                }
            }
        }
    }
#undef ISSUE

#pragma unroll
    for (int mt = 0; mt < 2; mt++){
        const int row0 = bm + wm*32 + mt*16 + (lane >> 2);
        if (EPI == 0){
#pragma unroll
            for (int nt = 0; nt < 8; nt++){
                const int col = bn + wn*64 + nt*8 + (lane & 3)*2;
                const float bx = bias[col], by = bias[col+1];
                float2 o0, o1;
                o0.x = acc[mt][nt][0] + bx;  o0.y = acc[mt][nt][1] + by;
                o1.x = acc[mt][nt][2] + bx;  o1.y = acc[mt][nt][3] + by;
                *reinterpret_cast<float2*>(C + (size_t)row0*DM + col) = o0;
                *reinterpret_cast<float2*>(C + (size_t)(row0+8)*DM + col) = o1;
            }
        } else {
            float s0 = 0.f, s1 = 0.f;
#pragma unroll
            for (int nt = 0; nt < 8; nt++){
                const int col = bn + wn*64 + nt*8 + (lane & 3)*2;
                const float bx = bias[col], by = bias[col+1];
                acc[mt][nt][0] += bx; acc[mt][nt][1] += by;
                acc[mt][nt][2] += bx; acc[mt][nt][3] += by;
                s0 += acc[mt][nt][0]*acc[mt][nt][0] + acc[mt][nt][1]*acc[mt][nt][1];
                s1 += acc[mt][nt][2]*acc[mt][nt][2] + acc[mt][nt][3]*acc[mt][nt][3];
            }
            s0 += __shfl_xor_sync(0xffffffffu, s0, 1);
            s0 += __shfl_xor_sync(0xffffffffu, s0, 2);
            s1 += __shfl_xor_sync(0xffffffffu, s1, 1);
            s1 += __shfl_xor_sync(0xffffffffu, s1, 2);
            const int head = (bn >> 6) + wn;
            const float g = __ldg(gamma + head);
            const float sc0 = g * rsqrtf(s0);
            const float sc1 = g * rsqrtf(s1);
#pragma unroll
            for (int nt = 0; nt < 8; nt++){
                const int col = bn + wn*64 + nt*8 + (lane & 3)*2;
                __half h0 = __float2half(acc[mt][nt][0]*sc0);
                __half h1 = __float2half(acc[mt][nt][1]*sc0);
                __half h2 = __float2half(acc[mt][nt][2]*sc1);
                __half h3 = __float2half(acc[mt][nt][3]*sc1);
                *reinterpret_cast<uint32_t*>(Oh + (size_t)row0*DM + col) =
                    (uint32_t)__half_as_ushort(h0) | ((uint32_t)__half_as_ushort(h1)<<16);
                *reinterpret_cast<uint32_t*>(Oh + (size_t)(row0+8)*DM + col) =
                    (uint32_t)__half_as_ushort(h2) | ((uint32_t)__half_as_ushort(h3)<<16);
            }
        }
    }
}

// ---------------- S GEMM body ----------------------------------------------------
static __device__ __forceinline__ void s_core(int b, int bm, int bn)
{
    extern __shared__ __half smbuf[];
    const uint32_t smu = s2u(smbuf);
    const int tid = threadIdx.x, lane = tid & 31, wid = tid >> 5;
    const int wm = wid & 3, wn = wid >> 2;
    const __half* Av = g_in[1] + (size_t)b*SEQ*DM;   // values
    const __half* Bk = g_in[0] + (size_t)b*SEQ*DM;   // keys

    const uint32_t t_off = (uint32_t)(((lane & 7) + ((lane >> 4) << 3)) * (S_LDSE*2))
                         + (uint32_t)(((lane >> 3) & 1) * 16);

    float acc[2][8][4];
#pragma unroll
    for (int i = 0; i < 2; i++)
#pragma unroll
        for (int j = 0; j < 8; j++)
#pragma unroll
            for (int q = 0; q < 4; q++) acc[i][j][q] = 0.f;

#define S_ISSUE(c_) do {                                                       \
        const int c__ = (c_);                                                  \
        const uint32_t sb = smu + (uint32_t)((c__ % 3) * S_STAGE);             \
        const int n0 = c__ * 64;                                               \
        _Pragma("unroll")                                                      \
        for (int arr = 0; arr < 2; arr++){                                     \
            const __half* s = (arr==0)?Av:Bk;                                  \
            const int col0 = (arr == 0) ? bm : bn;                             \
            const uint32_t ab = sb + (uint32_t)(arr * S_TB);                   \
            _Pragma("unroll")                                                  \
            for (int it = 0; it < 4; it++){                                    \
                int id = tid + it*NTHR;                                        \
                int r = id >> 4, cg = id & 15;                                 \
                cp16(ab + (uint32_t)(r*(S_LDSE*2) + cg*16),                    \
                     s + (size_t)(n0 + r)*DM + col0 + cg*8);                   \
            }                                                                  \
        }                                                                      \
        CP_COMMIT();                                                           \
    } while(0)

    S_ISSUE(0); S_ISSUE(1);
    for (int c = 0; c < S_NCH; c++){
        if (c + 1 < S_NCH) asm volatile("cp.async.wait_group 1;" ::: "memory");
        else               asm volatile("cp.async.wait_group 0;" ::: "memory");
        __syncthreads();
        if (c + 2 < S_NCH) S_ISSUE(c + 2);

        const uint32_t sb = smu + (uint32_t)((c % 3) * S_STAGE);
#pragma unroll
        for (int ks = 0; ks < 4; ks++){
            uint32_t bf[4][4];
#pragma unroll
            for (int np = 0; np < 4; np++)
                LDM4T(bf[np], sb + (uint32_t)S_TB + t_off
                      + (uint32_t)(ks*16*(S_LDSE*2)) + (uint32_t)((wn*64 + np*16)*2));
#pragma unroll
            for (int mt = 0; mt < 2; mt++){
                uint32_t af[4];
                LDM4T(af, sb + t_off + (uint32_t)(ks*16*(S_LDSE*2))
                      + (uint32_t)((wm*32 + mt*16)*2));
#pragma unroll
                for (int nt = 0; nt < 8; nt++){
                    const int np = nt >> 1, sub = nt & 1;
                    MMA(acc[mt][nt], af, bf[np][sub], bf[np][sub+2]);
                }
            }
        }
    }
#undef S_ISSUE

    __half* sth = g_sth[b];
    __half* stl = g_stl[b];
#pragma unroll
    for (int mt = 0; mt < 2; mt++){
        const int row0 = bm + wm*32 + mt*16 + (lane >> 2);
#pragma unroll
        for (int nt = 0; nt < 8; nt++){
            const int col = bn + wn*64 + nt*8 + (lane & 3)*2;
#pragma unroll
            for (int half = 0; half < 2; half++){
                const int row = row0 + half*8;
                float v0 = acc[mt][nt][half*2+0], v1 = acc[mt][nt][half*2+1];
                __half h0 = __float2half(v0), h1 = __float2half(v1);
                __half l0 = __float2half(v0 - __half2float(h0));
                __half l1 = __float2half(v1 - __half2float(h1));
                *reinterpret_cast<uint32_t*>(sth + (size_t)row*DM + col) =
                    (uint32_t)__half_as_ushort(h0) | ((uint32_t)__half_as_ushort(h1)<<16);
                *reinterpret_cast<uint32_t*>(stl + (size_t)row*DM + col) =
                    (uint32_t)__half_as_ushort(l0) | ((uint32_t)__half_as_ushort(l1)<<16);
            }
        }
    }
}

// ---------------- colsum body -------------------------------------------------
static __device__ __forceinline__ void colsum_core(int zi, int b, int seg, int xb)
{
    const int col = (xb * 256 + threadIdx.x) * 2;
    const int n0  = seg * (SEQ / CS_SEG);
    const __half2* p = reinterpret_cast<const __half2*>(
        g_in[zi] + (size_t)b*SEQ*DM + (size_t)n0*DM + col);
    float s0 = 0.f, s1 = 0.f;
    for (int n = 0; n < SEQ/CS_SEG; n += 8){
#pragma unroll
        for (int j = 0; j < 8; j++){
            float2 x = __half22float2(p[(size_t)(n+j)*(DM/2)]);
            s0 += x.x; s1 += x.y;
        }
    }
    atomicAdd(&g_cs[zi][b][col],     s0);
    atomicAdd(&g_cs[zi][b][col + 1], s1);
}

// ---------------- L2: combo = q-proj + s_mma + colsum ---------------------------
__global__ void __launch_bounds__(NTHR, 2) combo_mma(
    const float* __restrict__ queries,
    const float* __restrict__ bq, const float* __restrict__ gamma)
{
    const int bid = blockIdx.x;
    if (bid < N_PROJ){
        gemm_core<1, 1>(nullptr, queries, g_w[0], bq, gamma, nullptr, g_qn,
                        (bid >> 3) * BM, (bid & 7) * BN);
    } else if (bid < N_PROJ + N_S){
        const int r = bid - N_PROJ;
        const int b = r >> 6, rem = r & 63;
        s_core(b, (rem >> 3) * 128, (rem & 7) * 128);
    } else {
        const int c = bid - N_PROJ - N_S;
        const int zi = c >> 8, rem = c & 255;
        colsum_core(zi, (rem >> 1) / CS_SEG, (rem >> 1) % CS_SEG, rem & 1);
    }
}

// ---------------- T GEMM body + matvec body --------------------------------------
static __device__ __forceinline__ void t_core(int b, int bm, int bn)
{
    extern __shared__ __half smbuf[];
    const uint32_t smu = s2u(smbuf);
    const int tid = threadIdx.x, lane = tid & 31, wid = tid >> 5;
    const int wm = wid & 3, wn = wid >> 2;
    const __half* A  = g_w[1];
    const __half* Bh = g_sth[b];
    const __half* Bl = g_stl[b];

    const uint32_t a_off = (uint32_t)((wm*32 + (lane & 15))*LDS_ + (lane >> 4)*8)*2;
    const uint32_t b_off = (uint32_t)TB +
                           (uint32_t)((wn*64 + (lane & 15))*LDS_ + (lane >> 4)*8)*2;

    float acc[2][8][4];
#pragma unroll
    for (int i = 0; i < 2; i++)
#pragma unroll
        for (int j = 0; j < 8; j++)
#pragma unroll
            for (int q = 0; q < 4; q++) acc[i][j][q] = 0.f;

#define T_ISSUE(c_) do {                                                       \
        const int c__ = (c_);                                                  \
        const uint32_t sb = smu + (uint32_t)((c__ & 1) * T_STAGE);             \
        const int k0 = c__ * BK;                                               \
        _Pragma("unroll")                                                      \
        for (int arr = 0; arr < 3; arr++){                                     \
            const __half* s = (arr==0)?A:(arr==1)?Bh:Bl;                       \
            const int row0 = (arr == 0) ? bm : bn;                             \
            const uint32_t ab = sb + (uint32_t)(arr * TB);                     \
            _Pragma("unroll")                                                  \
            for (int it = 0; it < 4; it++){                                    \
                int id = tid + it*NTHR;                                        \
                int r = id >> 3, cg = id & 7;                                  \
                cp16(ab + (uint32_t)(r*LDS_ + cg*8)*2,                         \
                     s + (size_t)(row0 + r)*DM + k0 + cg*8);                   \
            }                                                                  \
        }                                                                      \
        CP_COMMIT();                                                           \
    } while(0)

    T_ISSUE(0);
    for (int c = 0; c < NCH; c++){
        if (c + 1 < NCH){
            T_ISSUE(c + 1);
            asm volatile("cp.async.wait_group 1;" ::: "memory");
        } else {
            asm volatile("cp.async.wait_group 0;" ::: "memory");
        }
        __syncthreads();
        const uint32_t sb = smu + (uint32_t)((c & 1) * T_STAGE);
#pragma unroll
        for (int ks = 0; ks < 4; ks++){
            uint32_t bfh[4][4], bfl[4][4];
#pragma unroll
            for (int np = 0; np < 4; np++){
                uint32_t bd = sb + b_off + (uint32_t)(np*16*LDS_ + ks*16)*2;
                LDM4(bfh[np], bd);
                LDM4(bfl[np], bd + (uint32_t)TB);
            }
#pragma unroll
            for (int mt = 0; mt < 2; mt++){
                uint32_t af[4];
                LDM4(af, sb + a_off + (uint32_t)(mt*16*LDS_ + ks*16)*2);
#pragma unroll
                for (int nt = 0; nt < 8; nt++){
                    const int np = nt >> 1, sub = nt & 1;
                    MMA(acc[mt][nt], af, bfh[np][sub], bfh[np][sub+2]);
                }
#pragma unroll
                for (int nt = 0; nt < 8; nt++){
                    const int np = nt >> 1, sub = nt & 1;
                    MMA(acc[mt][nt], af, bfl[np][sub], bfl[np][sub+2]);
                }
            }
        }
        __syncthreads();
    }
#undef T_ISSUE

    float* Tb = g_T + (size_t)b*DM*DM;
#pragma unroll
    for (int mt = 0; mt < 2; mt++){
        const int row0 = bm + wm*32 + mt*16 + (lane >> 2);
#pragma unroll
        for (int nt = 0; nt < 8; nt++){
            const int col = bn + wn*64 + nt*8 + (lane & 3)*2;
            float2 o0, o1;
            o0.x = acc[mt][nt][0]; o0.y = acc[mt][nt][1];
            o1.x = acc[mt][nt][2]; o1.y = acc[mt][nt][3];
            *reinterpret_cast<float2*>(Tb + (size_t)row0*DM + col) = o0;
            *reinterpret_cast<float2*>(Tb + (size_t)(row0+8)*DM + col) = o1;
        }
    }
}

static __device__ __forceinline__ void matvec_core(
    int z, int b, int xb, const float* __restrict__ Wk, const float* __restrict__ Wv)
{
    const float* W = (z == 0) ? Wk : Wv;
    const int wid = threadIdx.x >> 5, lane = threadIdx.x & 31;
    const int d = xb * 8 + wid;
    const float* wr = W + (size_t)d * DM;
    const float* cs = g_cs[z][b];
    float acc = 0.f;
#pragma unroll
    for (int i = 0; i < 8; i++){
        const int o = (lane + i*32) * 4;
        float4 a = *reinterpret_cast<const float4*>(wr + o);
        float4 c = *reinterpret_cast<const float4*>(cs + o);
        acc += a.x*c.x + a.y*c.y + a.z*c.z + a.w*c.w;
    }
    acc += __shfl_xor_sync(0xffffffffu, acc, 16);
    acc += __shfl_xor_sync(0xffffffffu, acc, 8);
    acc += __shfl_xor_sync(0xffffffffu, acc, 4);
    acc += __shfl_xor_sync(0xffffffffu, acc, 2);
    acc += __shfl_xor_sync(0xffffffffu, acc, 1);
    if (lane == 0) g_uv[z][b][d] = acc;
}

// ---------------- L3: t_combo = t_mma + matvec ----------------------------------
__global__ void __launch_bounds__(NTHR, 2) t_combo(
    const float* __restrict__ Wk, const float* __restrict__ Wv)
{
    const int bid = blockIdx.x;
    if (bid < N_T){
        const int b = bid >> 6, rem = bid & 63;
        t_core(b, (rem >> 3) * 128, (rem & 7) * 128);
    } else {
        const int m = bid - N_T;
        matvec_core(m >> 9, (m & 511) >> 7, m & 127, Wk, Wv);
    }
}

// ---------------- L1: conv_all = conv_kv + conv_w + zero_cs + zero_kv ------------
__global__ void __launch_bounds__(256) conv_all(
    const float* __restrict__ k, const float* __restrict__ v,
    const float* __restrict__ wq, const float* __restrict__ wk)
{
    const int bid = blockIdx.x;
    if (bid < N_CI){
        const int z = bid / (N_CI/2), x = bid % (N_CI/2);
        const float* s = (z == 0) ? k : v;
        size_t i4 = (size_t)x * 256 + threadIdx.x;
        float4 xx = *reinterpret_cast<const float4*>(s + i4*4);
        __half h[4] = {__float2half(xx.x), __float2half(xx.y),
                       __float2half(xx.z), __float2half(xx.w)};
        *reinterpret_cast<uint2*>(&g_in[z][i4*4]) = make_uint2(
            (uint32_t)__half_as_ushort(h[0]) | ((uint32_t)__half_as_ushort(h[1])<<16),
            (uint32_t)__half_as_ushort(h[2]) | ((uint32_t)__half_as_ushort(h[3])<<16));
    } else if (bid < N_CI + N_CW){
        const int r = bid - N_CI;
        const int z = r / (N_CW/2), x = r % (N_CW/2);
        const float* s = (z == 0) ? wq : wk;
        size_t i4 = (size_t)x * 256 + threadIdx.x;
        float4 xx = *reinterpret_cast<const float4*>(s + i4*4);
        __half h[4] = {__float2half(xx.x), __float2half(xx.y),
                       __float2half(xx.z), __float2half(xx.w)};
        *reinterpret_cast<uint2*>(&g_w[z][i4*4]) = make_uint2(
            (uint32_t)__half_as_ushort(h[0]) | ((uint32_t)__half_as_ushort(h[1])<<16),
            (uint32_t)__half_as_ushort(h[2]) | ((uint32_t)__half_as_ushort(h[3])<<16));
    } else if (bid < N_CI + N_CW + N_ZC){
        const int r = bid - N_CI - N_CW;
        int i = r * 256 + threadIdx.x;
        if (i < 2*BATCH*DM) ((float*)g_cs)[i] = 0.f;
    } else {
        const int r = bid - N_CI - N_CW - N_ZC;
        g_kv[r * 256 + threadIdx.x] = 0.f;
    }
}

// ---------------- out GEMM -------------------------------------------------------
__global__ void __launch_bounds__(NTHR, 2) out_mma(
    const float* __restrict__ bo, float* __restrict__ out)
{
    const int b = blockIdx.z;
    gemm_core<0, 0>(g_qn + (size_t)b*SEQ*DM, nullptr, g_w2 + (size_t)b*DM*DM,
                    bo, nullptr, out + (size_t)b*SEQ*DM, nullptr,
                    blockIdx.y * BM, blockIdx.x * BN);
}

// ---------------- kv_small: K-split, stride-69 smem (2-way max conflicts) --------
__global__ void __launch_bounds__(256) kv_small(
    const float* __restrict__ Wv,
    const float* __restrict__ bk, const float* __restrict__ bv)
{
    const int bh = blockIdx.x, seg = blockIdx.y;
    const int b = bh >> 4, h = bh & 15;
    __shared__ float Ts[64][69];
    __shared__ float Ws[64][69];
    const int tid = threadIdx.x;
    const int ti = tid >> 4, tj = tid & 15;
    const float* Tb = g_T + (size_t)b*DM*DM + (size_t)(h*64)*DM;
    const float* Wb = Wv + (size_t)(h*64)*DM;
    const int seg0 = seg * (DM / KV_SEG);

    float acc[4][4];
#pragma unroll
    for (int i = 0; i < 4; i++)
#pragma unroll
        for (int j = 0; j < 4; j++) acc[i][j] = 0.f;

    for (int i0 = seg0; i0 < seg0 + DM/KV_SEG; i0 += 64){
#pragma unroll
        for (int it = 0; it < 4; it++){
            int id = tid + it*256;
            int r = id >> 4, c4 = (id & 15)*4;
            float4 tv = *reinterpret_cast<const float4*>(Tb + (size_t)r*DM + i0 + c4);
            float4 wv = *reinterpret_cast<const float4*>(Wb + (size_t)r*DM + i0 + c4);
            Ts[r][c4+0] = tv.x; Ts[r][c4+1] = tv.y; Ts[r][c4+2] = tv.z; Ts[r][c4+3] = tv.w;
            Ws[r][c4+0] = wv.x; Ws[r][c4+1] = wv.y; Ws[r][c4+2] = wv.z; Ws[r][c4+3] = wv.w;
        }
        __syncthreads();
#pragma unroll 8
        for (int i = 0; i < 64; i++){
            float ta[4], wb_[4];
#pragma unroll
            for (int a = 0; a < 4; a++) ta[a]  = Ts[ti*4+a][i];
#pragma unroll
            for (int e = 0; e < 4; e++) wb_[e] = Ws[tj*4+e][i];
#pragma unroll
            for (int a = 0; a < 4; a++)
#pragma unroll
                for (int e = 0; e < 4; e++) acc[a][e] += ta[a] * wb_[e];
        }
        __syncthreads();
    }

    float* kvp = g_kv + (size_t)bh * 4096;
#pragma unroll
    for (int a = 0; a < 4; a++){
        const int d = ti*4 + a;
#pragma unroll
        for (int e4 = 0; e4 < 4; e4++){
            const int e = tj*4 + e4;
            float add = acc[a][e4];
            if (seg == 0){
                const float bkd = bk[h*64 + d];
                const float ud  = g_uv[0][b][h*64 + d];
                const float bve = bv[h*64 + e];
                const float we  = g_uv[1][b][h*64 + e];
                add += ud*bve + bkd*we + (float)SEQ*bkd*bve;
            }
            atomicAdd(&kvp[d*64 + e], add);
        }
    }
}

// ---------------- fold: xnorm(kv) @ Wo^T -> W2 (fp16), 16 j-slices ---------------
__global__ void __launch_bounds__(256) fold_kernel(
    const float* __restrict__ Wo, const float* __restrict__ gamma)
{
    const int bh = blockIdx.x, jc = blockIdx.y;
    const int b = bh >> 4, h = bh & 15;
    const int j0 = jc * 64;
    __shared__ float kvn[64][65];
    __shared__ float rn[64];
    const int tid = threadIdx.x;
    const float* kvsrc = g_kv + (size_t)bh * 4096;
    for (int l = tid; l < 4096; l += 256) kvn[l>>6][l&63] = kvsrc[l];
    __syncthreads();
    if (tid < 64){
        float s = 0.f;
#pragma unroll 16
        for (int d = 0; d < 64; d++){ float x = kvn[tid][d]; s += x*x; }
        rn[tid] = gamma[h] * rsqrtf(s);
    }
    __syncthreads();
    const int i = tid & 63, jg = tid >> 6;
    const float sc = rn[i];
    __half* w2 = g_w2 + (size_t)b*DM*DM;
    for (int j = jg; j < 64; j += 4){
        const float* wr = Wo + (size_t)(j0+j)*DM + h*64;
        float acc = 0.f;
#pragma unroll 16
        for (int d = 0; d < 64; d++) acc += kvn[i][d] * __ldg(wr + d);
        w2[(size_t)(j0+j)*DM + h*64 + i] = __float2half(acc * sc);
    }
}

// ---------------- launch ----------------------------------------------------------
extern "C" void kernel_launch(void* const* d_in, const int* in_sizes, int n_in,
                              void* d_out, int out_size)
{
    const float* queries = (const float*)d_in[0];
    const float* keys    = (const float*)d_in[1];
    const float* values  = (const float*)d_in[2];
    const float* Wq = (const float*)d_in[3];
    const float* bq = (const float*)d_in[4];
    const float* Wk = (const float*)d_in[5];
    const float* bk = (const float*)d_in[6];
    const float* Wv = (const float*)d_in[7];
    const float* bv = (const float*)d_in[8];
    const float* Wo = (const float*)d_in[9];
    const float* bo = (const float*)d_in[10];
    const float* gamma = (const float*)d_in[11];
    float* out = (float*)d_out;

    cudaFuncSetAttribute(combo_mma, cudaFuncAttributeMaxDynamicSharedMemorySize, DYN);
    cudaFuncSetAttribute(t_combo,   cudaFuncAttributeMaxDynamicSharedMemorySize, T_DYN);
    cudaFuncSetAttribute(out_mma,   cudaFuncAttributeMaxDynamicSharedMemorySize, DYN);

    conv_all<<<CONV_GRID, 256>>>(keys, values, Wq, Wk);
    combo_mma<<<COMBO_GRID, NTHR, DYN>>>(queries, bq, gamma);
    t_combo<<<TCOMBO_GRID, NTHR, T_DYN>>>(Wk, Wv);
    kv_small<<<dim3(BATCH*H, KV_SEG), 256>>>(Wv, bk, bv);
    fold_kernel<<<dim3(BATCH*H, 16), 256>>>(Wo, gamma);
    out_mma<<<dim3(DM/BN, SEQ/BM, BATCH), NTHR, DYN>>>(bo, out);
}

// round 17
// speedup vs baseline: 1.0491x; 1.0491x over previous
#include <cuda_runtime.h>
#include <cuda_fp16.h>
#include <cstdint>

#define DM 1024
#define H 16
#define BATCH 4
#define SEQ 8192
#define MTOT (BATCH*SEQ)

// ---- standard GEMM: CTA 128x128, warp 32x64, 3 stages ----
#define BM 128
#define BN 128
#define BK 64
#define NCH (DM/BK)
#define LDS_ 72
#define TB (128*LDS_*2)
#define STAGE_B (2*TB)
#define DYN (3*STAGE_B)         // 110592 -> 2 CTAs/SM
#define NTHR 256

// ---- S GEMM ----
#define S_LDSE 136
#define S_TB (64*S_LDSE*2)
#define S_STAGE (2*S_TB)
#define S_NCH (SEQ/64)

// ---- T GEMM ----
#define T_STAGE (3*TB)
#define T_DYN (2*T_STAGE)       // 110592

#define CS_SEG 32
#define KV_SEG 8

// grid split constants
#define N_PROJ 2048
#define N_S    256
#define N_CS   512
#define COMBO_GRID (N_PROJ + N_S + N_CS)
#define N_T    256
#define N_MV   1024
#define TCOMBO_GRID (N_T + N_MV)
#define N_CI   (3*((MTOT*DM/4)/256))   // 98304
#define N_CW   (2*((DM*DM/4)/256))     // 2048
#define N_ZC   ((2*BATCH*DM)/256)      // 32
#define N_ZKV  ((BATCH*H*64*64)/256)   // 1024
#define CONV_GRID (N_CI + N_CW + N_ZC + N_ZKV)

// ---------------- scratch ----------------------------------------------------
__device__ __half g_in[3][(size_t)MTOT*DM];
__device__ __half g_w[2][DM*DM];
__device__ __half g_qn[(size_t)MTOT*DM];
__device__ __half g_w2[(size_t)BATCH*DM*DM];
__device__ __half g_sth[BATCH][DM*DM];
__device__ __half g_stl[BATCH][DM*DM];
__device__ float  g_T[(size_t)BATCH*DM*DM];
__device__ float  g_kv[BATCH*H*64*64];
__device__ float  g_cs[2][BATCH][DM];
__device__ float  g_uv[2][BATCH][DM];

// ---------------- helpers ------------------------------------------------------
static __device__ __forceinline__ uint32_t s2u(const void* p){
    uint32_t r;
    asm("{ .reg .u64 t; cvta.to.shared.u64 t, %1; cvt.u32.u64 %0, t; }" : "=r"(r) : "l"(p));
    return r;
}
static __device__ __forceinline__ void cp16(uint32_t dst, const void* src){
    asm volatile("cp.async.cg.shared.global [%0], [%1], 16;" :: "r"(dst), "l"(src));
}
#define CP_COMMIT() asm volatile("cp.async.commit_group;" ::: "memory")
#define LDM4(r, a) asm volatile( \
    "ldmatrix.sync.aligned.m8n8.x4.shared.b16 {%0,%1,%2,%3}, [%4];" \
    : "=r"((r)[0]),"=r"((r)[1]),"=r"((r)[2]),"=r"((r)[3]) : "r"(a))
#define LDM4T(r, a) asm volatile( \
    "ldmatrix.sync.aligned.m8n8.x4.trans.shared.b16 {%0,%1,%2,%3}, [%4];" \
    : "=r"((r)[0]),"=r"((r)[1]),"=r"((r)[2]),"=r"((r)[3]) : "r"(a))
#define MMA(d, a, b0_, b1_) asm volatile( \
    "mma.sync.aligned.m16n8k16.row.col.f32.f16.f16.f32 " \
    "{%0,%1,%2,%3},{%4,%5,%6,%7},{%8,%9},{%0,%1,%2,%3};" \
    : "+f"((d)[0]),"+f"((d)[1]),"+f"((d)[2]),"+f"((d)[3]) \
    : "r"((a)[0]),"r"((a)[1]),"r"((a)[2]),"r"((a)[3]), "r"(b0_),"r"(b1_))

// ---------------- fp16 GEMM core (3-stage, single sync) ------------------------
template<int EPI>
static __device__ __forceinline__ void gemm_core(
    const __half* __restrict__ Ah, const __half* __restrict__ Bh,
    const float* __restrict__ bias, const float* __restrict__ gamma,
    float* __restrict__ C, __half* __restrict__ Oh, int bm, int bn)
{
    extern __shared__ __half smbuf[];
    const uint32_t smu = s2u(smbuf);
    const int tid = threadIdx.x, lane = tid & 31, wid = tid >> 5;
    const int wm = wid & 3, wn = wid >> 2;

    const uint32_t a_off = (uint32_t)((wm*32 + (lane & 15))*LDS_ + (lane >> 4)*8)*2;
    const uint32_t b_off = (uint32_t)TB +
                           (uint32_t)((wn*64 + (lane & 15))*LDS_ + (lane >> 4)*8)*2;

    float acc[2][8][4];
#pragma unroll
    for (int i = 0; i < 2; i++)
#pragma unroll
        for (int j = 0; j < 8; j++)
#pragma unroll
            for (int q = 0; q < 4; q++) acc[i][j][q] = 0.f;

#define ISSUE(c_) do {                                                         \
        const int c__ = (c_);                                                  \
        const uint32_t sb = smu + (uint32_t)((c__ % 3) * STAGE_B);             \
        const int k0 = c__ * BK;                                               \
        _Pragma("unroll")                                                      \
        for (int arr = 0; arr < 2; arr++){                                     \
            const __half* s = (arr==0)?Ah:Bh;                                  \
            const int row0 = (arr == 0) ? bm : bn;                             \
            const uint32_t ab = sb + (uint32_t)(arr * TB);                     \
            _Pragma("unroll")                                                  \
            for (int it = 0; it < 4; it++){                                    \
                int id = tid + it*NTHR;                                        \
                int r = id >> 3, cg = id & 7;                                  \
                cp16(ab + (uint32_t)(r*LDS_ + cg*8)*2,                         \
                     s + (size_t)(row0 + r)*DM + k0 + cg*8);                   \
            }                                                                  \
        }                                                                      \
        CP_COMMIT();                                                           \
    } while(0)

    ISSUE(0); ISSUE(1);
    for (int c = 0; c < NCH; c++){
        if (c + 1 < NCH) asm volatile("cp.async.wait_group 1;" ::: "memory");
        else             asm volatile("cp.async.wait_group 0;" ::: "memory");
        __syncthreads();
        if (c + 2 < NCH) ISSUE(c + 2);

        const uint32_t sb = smu + (uint32_t)((c % 3) * STAGE_B);
#pragma unroll
        for (int ks = 0; ks < 4; ks++){
            uint32_t bf[4][4];
#pragma unroll
            for (int np = 0; np < 4; np++)
                LDM4(bf[np], sb + b_off + (uint32_t)(np*16*LDS_ + ks*16)*2);
#pragma unroll
            for (int mt = 0; mt < 2; mt++){
                uint32_t af[4];
                LDM4(af, sb + a_off + (uint32_t)(mt*16*LDS_ + ks*16)*2);
#pragma unroll
                for (int nt = 0; nt < 8; nt++){
                    const int np = nt >> 1, sub = nt & 1;
                    MMA(acc[mt][nt], af, bf[np][sub], bf[np][sub+2]);
                }
            }
        }
    }
#undef ISSUE

#pragma unroll
    for (int mt = 0; mt < 2; mt++){
        const int row0 = bm + wm*32 + mt*16 + (lane >> 2);
        if (EPI == 0){
#pragma unroll
            for (int nt = 0; nt < 8; nt++){
                const int col = bn + wn*64 + nt*8 + (lane & 3)*2;
                const float bx = bias[col], by = bias[col+1];
                float2 o0, o1;
                o0.x = acc[mt][nt][0] + bx;  o0.y = acc[mt][nt][1] + by;
                o1.x = acc[mt][nt][2] + bx;  o1.y = acc[mt][nt][3] + by;
                *reinterpret_cast<float2*>(C + (size_t)row0*DM + col) = o0;
                *reinterpret_cast<float2*>(C + (size_t)(row0+8)*DM + col) = o1;
            }
        } else {
            float s0 = 0.f, s1 = 0.f;
#pragma unroll
            for (int nt = 0; nt < 8; nt++){
                const int col = bn + wn*64 + nt*8 + (lane & 3)*2;
                const float bx = bias[col], by = bias[col+1];
                acc[mt][nt][0] += bx; acc[mt][nt][1] += by;
                acc[mt][nt][2] += bx; acc[mt][nt][3] += by;
                s0 += acc[mt][nt][0]*acc[mt][nt][0] + acc[mt][nt][1]*acc[mt][nt][1];
                s1 += acc[mt][nt][2]*acc[mt][nt][2] + acc[mt][nt][3]*acc[mt][nt][3];
            }
            s0 += __shfl_xor_sync(0xffffffffu, s0, 1);
            s0 += __shfl_xor_sync(0xffffffffu, s0, 2);
            s1 += __shfl_xor_sync(0xffffffffu, s1, 1);
            s1 += __shfl_xor_sync(0xffffffffu, s1, 2);
            const int head = (bn >> 6) + wn;
            const float g = __ldg(gamma + head);
            const float sc0 = g * rsqrtf(s0);
            const float sc1 = g * rsqrtf(s1);
#pragma unroll
            for (int nt = 0; nt < 8; nt++){
                const int col = bn + wn*64 + nt*8 + (lane & 3)*2;
                __half h0 = __float2half(acc[mt][nt][0]*sc0);
                __half h1 = __float2half(acc[mt][nt][1]*sc0);
                __half h2 = __float2half(acc[mt][nt][2]*sc1);
                __half h3 = __float2half(acc[mt][nt][3]*sc1);
                *reinterpret_cast<uint32_t*>(Oh + (size_t)row0*DM + col) =
                    (uint32_t)__half_as_ushort(h0) | ((uint32_t)__half_as_ushort(h1)<<16);
                *reinterpret_cast<uint32_t*>(Oh + (size_t)(row0+8)*DM + col) =
                    (uint32_t)__half_as_ushort(h2) | ((uint32_t)__half_as_ushort(h3)<<16);
            }
        }
    }
}

// ---------------- S GEMM body ----------------------------------------------------
static __device__ __forceinline__ void s_core(int b, int bm, int bn)
{
    extern __shared__ __half smbuf[];
    const uint32_t smu = s2u(smbuf);
    const int tid = threadIdx.x, lane = tid & 31, wid = tid >> 5;
    const int wm = wid & 3, wn = wid >> 2;
    const __half* Av = g_in[2] + (size_t)b*SEQ*DM;
    const __half* Bk = g_in[1] + (size_t)b*SEQ*DM;

    const uint32_t t_off = (uint32_t)(((lane & 7) + ((lane >> 4) << 3)) * (S_LDSE*2))
                         + (uint32_t)(((lane >> 3) & 1) * 16);

    float acc[2][8][4];
#pragma unroll
    for (int i = 0; i < 2; i++)
#pragma unroll
        for (int j = 0; j < 8; j++)
#pragma unroll
            for (int q = 0; q < 4; q++) acc[i][j][q] = 0.f;

#define S_ISSUE(c_) do {                                                       \
        const int c__ = (c_);                                                  \
        const uint32_t sb = smu + (uint32_t)((c__ % 3) * S_STAGE);             \
        const int n0 = c__ * 64;                                               \
        _Pragma("unroll")                                                      \
        for (int arr = 0; arr < 2; arr++){                                     \
            const __half* s = (arr==0)?Av:Bk;                                  \
            const int col0 = (arr == 0) ? bm : bn;                             \
            const uint32_t ab = sb + (uint32_t)(arr * S_TB);                   \
            _Pragma("unroll")                                                  \
            for (int it = 0; it < 4; it++){                                    \
                int id = tid + it*NTHR;                                        \
                int r = id >> 4, cg = id & 15;                                 \
                cp16(ab + (uint32_t)(r*(S_LDSE*2) + cg*16),                    \
                     s + (size_t)(n0 + r)*DM + col0 + cg*8);                   \
            }                                                                  \
        }                                                                      \
        CP_COMMIT();                                                           \
    } while(0)

    S_ISSUE(0); S_ISSUE(1);
    for (int c = 0; c < S_NCH; c++){
        if (c + 1 < S_NCH) asm volatile("cp.async.wait_group 1;" ::: "memory");
        else               asm volatile("cp.async.wait_group 0;" ::: "memory");
        __syncthreads();
        if (c + 2 < S_NCH) S_ISSUE(c + 2);

        const uint32_t sb = smu + (uint32_t)((c % 3) * S_STAGE);
#pragma unroll
        for (int ks = 0; ks < 4; ks++){
            uint32_t bf[4][4];
#pragma unroll
            for (int np = 0; np < 4; np++)
                LDM4T(bf[np], sb + (uint32_t)S_TB + t_off
                      + (uint32_t)(ks*16*(S_LDSE*2)) + (uint32_t)((wn*64 + np*16)*2));
#pragma unroll
            for (int mt = 0; mt < 2; mt++){
                uint32_t af[4];
                LDM4T(af, sb + t_off + (uint32_t)(ks*16*(S_LDSE*2))
                      + (uint32_t)((wm*32 + mt*16)*2));
#pragma unroll
                for (int nt = 0; nt < 8; nt++){
                    const int np = nt >> 1, sub = nt & 1;
                    MMA(acc[mt][nt], af, bf[np][sub], bf[np][sub+2]);
                }
            }
        }
    }
#undef S_ISSUE

    __half* sth = g_sth[b];
    __half* stl = g_stl[b];
#pragma unroll
    for (int mt = 0; mt < 2; mt++){
        const int row0 = bm + wm*32 + mt*16 + (lane >> 2);
#pragma unroll
        for (int nt = 0; nt < 8; nt++){
            const int col = bn + wn*64 + nt*8 + (lane & 3)*2;
#pragma unroll
            for (int half = 0; half < 2; half++){
                const int row = row0 + half*8;
                float v0 = acc[mt][nt][half*2+0], v1 = acc[mt][nt][half*2+1];
                __half h0 = __float2half(v0), h1 = __float2half(v1);
                __half l0 = __float2half(v0 - __half2float(h0));
                __half l1 = __float2half(v1 - __half2float(h1));
                *reinterpret_cast<uint32_t*>(sth + (size_t)row*DM + col) =
                    (uint32_t)__half_as_ushort(h0) | ((uint32_t)__half_as_ushort(h1)<<16);
                *reinterpret_cast<uint32_t*>(stl + (size_t)row*DM + col) =
                    (uint32_t)__half_as_ushort(l0) | ((uint32_t)__half_as_ushort(l1)<<16);
            }
        }
    }
}

// ---------------- colsum body -------------------------------------------------
static __device__ __forceinline__ void colsum_core(int zi, int b, int seg, int xb)
{
    const int col = (xb * 256 + threadIdx.x) * 2;
    const int n0  = seg * (SEQ / CS_SEG);
    const __half2* p = reinterpret_cast<const __half2*>(
        g_in[1 + zi] + (size_t)b*SEQ*DM + (size_t)n0*DM + col);
    float s0 = 0.f, s1 = 0.f;
    for (int n = 0; n < SEQ/CS_SEG; n += 8){
#pragma unroll
        for (int j = 0; j < 8; j++){
            float2 x = __half22float2(p[(size_t)(n+j)*(DM/2)]);
            s0 += x.x; s1 += x.y;
        }
    }
    atomicAdd(&g_cs[zi][b][col],     s0);
    atomicAdd(&g_cs[zi][b][col + 1], s1);
}

// ---------------- L2: combo = q-proj + s_mma + colsum ---------------------------
__global__ void __launch_bounds__(NTHR, 2) combo_mma(
    const float* __restrict__ bq, const float* __restrict__ gamma)
{
    const int bid = blockIdx.x;
    if (bid < N_PROJ){
        gemm_core<1>(g_in[0], g_w[0], bq, gamma, nullptr, g_qn,
                     (bid >> 3) * BM, (bid & 7) * BN);
    } else if (bid < N_PROJ + N_S){
        const int r = bid - N_PROJ;
        const int b = r >> 6, rem = r & 63;
        s_core(b, (rem >> 3) * 128, (rem & 7) * 128);
    } else {
        const int c = bid - N_PROJ - N_S;
        const int zi = c >> 8, rem = c & 255;
        colsum_core(zi, (rem >> 1) / CS_SEG, (rem >> 1) % CS_SEG, rem & 1);
    }
}

// ---------------- T GEMM body + matvec body --------------------------------------
static __device__ __forceinline__ void t_core(int b, int bm, int bn)
{
    extern __shared__ __half smbuf[];
    const uint32_t smu = s2u(smbuf);
    const int tid = threadIdx.x, lane = tid & 31, wid = tid >> 5;
    const int wm = wid & 3, wn = wid >> 2;
    const __half* A  = g_w[1];
    const __half* Bh = g_sth[b];
    const __half* Bl = g_stl[b];

    const uint32_t a_off = (uint32_t)((wm*32 + (lane & 15))*LDS_ + (lane >> 4)*8)*2;
    const uint32_t b_off = (uint32_t)TB +
                           (uint32_t)((wn*64 + (lane & 15))*LDS_ + (lane >> 4)*8)*2;

    float acc[2][8][4];
#pragma unroll
    for (int i = 0; i < 2; i++)
#pragma unroll
        for (int j = 0; j < 8; j++)
#pragma unroll
            for (int q = 0; q < 4; q++) acc[i][j][q] = 0.f;

#define T_ISSUE(c_) do {                                                       \
        const int c__ = (c_);                                                  \
        const uint32_t sb = smu + (uint32_t)((c__ & 1) * T_STAGE);             \
        const int k0 = c__ * BK;                                               \
        _Pragma("unroll")                                                      \
        for (int arr = 0; arr < 3; arr++){                                     \
            const __half* s = (arr==0)?A:(arr==1)?Bh:Bl;                       \
            const int row0 = (arr == 0) ? bm : bn;                             \
            const uint32_t ab = sb + (uint32_t)(arr * TB);                     \
            _Pragma("unroll")                                                  \
            for (int it = 0; it < 4; it++){                                    \
                int id = tid + it*NTHR;                                        \
                int r = id >> 3, cg = id & 7;                                  \
                cp16(ab + (uint32_t)(r*LDS_ + cg*8)*2,                         \
                     s + (size_t)(row0 + r)*DM + k0 + cg*8);                   \
            }                                                                  \
        }                                                                      \
        CP_COMMIT();                                                           \
    } while(0)

    T_ISSUE(0);
    for (int c = 0; c < NCH; c++){
        if (c + 1 < NCH){
            T_ISSUE(c + 1);
            asm volatile("cp.async.wait_group 1;" ::: "memory");
        } else {
            asm volatile("cp.async.wait_group 0;" ::: "memory");
        }
        __syncthreads();
        const uint32_t sb = smu + (uint32_t)((c & 1) * T_STAGE);
#pragma unroll
        for (int ks = 0; ks < 4; ks++){
            uint32_t bfh[4][4], bfl[4][4];
#pragma unroll
            for (int np = 0; np < 4; np++){
                uint32_t bd = sb + b_off + (uint32_t)(np*16*LDS_ + ks*16)*2;
                LDM4(bfh[np], bd);
                LDM4(bfl[np], bd + (uint32_t)TB);
            }
#pragma unroll
            for (int mt = 0; mt < 2; mt++){
                uint32_t af[4];
                LDM4(af, sb + a_off + (uint32_t)(mt*16*LDS_ + ks*16)*2);
#pragma unroll
                for (int nt = 0; nt < 8; nt++){
                    const int np = nt >> 1, sub = nt & 1;
                    MMA(acc[mt][nt], af, bfh[np][sub], bfh[np][sub+2]);
                }
#pragma unroll
                for (int nt = 0; nt < 8; nt++){
                    const int np = nt >> 1, sub = nt & 1;
                    MMA(acc[mt][nt], af, bfl[np][sub], bfl[np][sub+2]);
                }
            }
        }
        __syncthreads();
    }
#undef T_ISSUE

    float* Tb = g_T + (size_t)b*DM*DM;
#pragma unroll
    for (int mt = 0; mt < 2; mt++){
        const int row0 = bm + wm*32 + mt*16 + (lane >> 2);
#pragma unroll
        for (int nt = 0; nt < 8; nt++){
            const int col = bn + wn*64 + nt*8 + (lane & 3)*2;
            float2 o0, o1;
            o0.x = acc[mt][nt][0]; o0.y = acc[mt][nt][1];
            o1.x = acc[mt][nt][2]; o1.y = acc[mt][nt][3];
            *reinterpret_cast<float2*>(Tb + (size_t)row0*DM + col) = o0;
            *reinterpret_cast<float2*>(Tb + (size_t)(row0+8)*DM + col) = o1;
        }
    }
}

static __device__ __forceinline__ void matvec_core(
    int z, int b, int xb, const float* __restrict__ Wk, const float* __restrict__ Wv)
{
    const float* W = (z == 0) ? Wk : Wv;
    const int wid = threadIdx.x >> 5, lane = threadIdx.x & 31;
    const int d = xb * 8 + wid;
    const float* wr = W + (size_t)d * DM;
    const float* cs = g_cs[z][b];
    float acc = 0.f;
#pragma unroll
    for (int i = 0; i < 8; i++){
        const int o = (lane + i*32) * 4;
        float4 a = *reinterpret_cast<const float4*>(wr + o);
        float4 c = *reinterpret_cast<const float4*>(cs + o);
        acc += a.x*c.x + a.y*c.y + a.z*c.z + a.w*c.w;
    }
    acc += __shfl_xor_sync(0xffffffffu, acc, 16);
    acc += __shfl_xor_sync(0xffffffffu, acc, 8);
    acc += __shfl_xor_sync(0xffffffffu, acc, 4);
    acc += __shfl_xor_sync(0xffffffffu, acc, 2);
    acc += __shfl_xor_sync(0xffffffffu, acc, 1);
    if (lane == 0) g_uv[z][b][d] = acc;
}

// ---------------- L3: t_combo = t_mma + matvec ----------------------------------
__global__ void __launch_bounds__(NTHR, 2) t_combo(
    const float* __restrict__ Wk, const float* __restrict__ Wv)
{
    const int bid = blockIdx.x;
    if (bid < N_T){
        const int b = bid >> 6, rem = bid & 63;
        t_core(b, (rem >> 3) * 128, (rem & 7) * 128);
    } else {
        const int m = bid - N_T;
        matvec_core(m >> 9, (m & 511) >> 7, m & 127, Wk, Wv);
    }
}

// ---------------- L1: conv_all = conv_in + conv_w + zero_cs + zero_kv ------------
__global__ void __launch_bounds__(256) conv_all(
    const float* __restrict__ q, const float* __restrict__ k, const float* __restrict__ v,
    const float* __restrict__ wq, const float* __restrict__ wk)
{
    const int bid = blockIdx.x;
    if (bid < N_CI){
        const int z = bid / (N_CI/3), x = bid % (N_CI/3);
        const float* s = (z == 0) ? q : (z == 1) ? k : v;
        size_t i4 = (size_t)x * 256 + threadIdx.x;
        float4 xx = *reinterpret_cast<const float4*>(s + i4*4);
        __half h[4] = {__float2half(xx.x), __float2half(xx.y),
                       __float2half(xx.z), __float2half(xx.w)};
        *reinterpret_cast<uint2*>(&g_in[z][i4*4]) = make_uint2(
            (uint32_t)__half_as_ushort(h[0]) | ((uint32_t)__half_as_ushort(h[1])<<16),
            (uint32_t)__half_as_ushort(h[2]) | ((uint32_t)__half_as_ushort(h[3])<<16));
    } else if (bid < N_CI + N_CW){
        const int r = bid - N_CI;
        const int z = r / (N_CW/2), x = r % (N_CW/2);
        const float* s = (z == 0) ? wq : wk;
        size_t i4 = (size_t)x * 256 + threadIdx.x;
        float4 xx = *reinterpret_cast<const float4*>(s + i4*4);
        __half h[4] = {__float2half(xx.x), __float2half(xx.y),
                       __float2half(xx.z), __float2half(xx.w)};
        *reinterpret_cast<uint2*>(&g_w[z][i4*4]) = make_uint2(
            (uint32_t)__half_as_ushort(h[0]) | ((uint32_t)__half_as_ushort(h[1])<<16),
            (uint32_t)__half_as_ushort(h[2]) | ((uint32_t)__half_as_ushort(h[3])<<16));
    } else if (bid < N_CI + N_CW + N_ZC){
        const int r = bid - N_CI - N_CW;
        int i = r * 256 + threadIdx.x;
        if (i < 2*BATCH*DM) ((float*)g_cs)[i] = 0.f;
    } else {
        const int r = bid - N_CI - N_CW - N_ZC;
        g_kv[r * 256 + threadIdx.x] = 0.f;
    }
}

// ---------------- out GEMM -------------------------------------------------------
__global__ void __launch_bounds__(NTHR, 2) out_mma(
    const float* __restrict__ bo, float* __restrict__ out)
{
    const int b = blockIdx.z;
    gemm_core<0>(g_qn + (size_t)b*SEQ*DM, g_w2 + (size_t)b*DM*DM, bo, nullptr,
                 out + (size_t)b*SEQ*DM, nullptr, blockIdx.y * BM, blockIdx.x * BN);
}

// ---------------- kv_small: K-split, stride-69 smem (conflict-free-ish) ----------
__global__ void __launch_bounds__(256) kv_small(
    const float* __restrict__ Wv,
    const float* __restrict__ bk, const float* __restrict__ bv)
{
    const int bh = blockIdx.x, seg = blockIdx.y;
    const int b = bh >> 4, h = bh & 15;
    __shared__ float Ts[64][69];
    __shared__ float Ws[64][69];
    const int tid = threadIdx.x;
    const int ti = tid >> 4, tj = tid & 15;
    const float* Tb = g_T + (size_t)b*DM*DM + (size_t)(h*64)*DM;
    const float* Wb = Wv + (size_t)(h*64)*DM;
    const int seg0 = seg * (DM / KV_SEG);

    float acc[4][4];
#pragma unroll
    for (int i = 0; i < 4; i++)
#pragma unroll
        for (int j = 0; j < 4; j++) acc[i][j] = 0.f;

    for (int i0 = seg0; i0 < seg0 + DM/KV_SEG; i0 += 64){
#pragma unroll
        for (int it = 0; it < 4; it++){
            int id = tid + it*256;
            int r = id >> 4, c4 = (id & 15)*4;
            float4 tv = *reinterpret_cast<const float4*>(Tb + (size_t)r*DM + i0 + c4);
            float4 wv = *reinterpret_cast<const float4*>(Wb + (size_t)r*DM + i0 + c4);
            Ts[r][c4+0] = tv.x; Ts[r][c4+1] = tv.y; Ts[r][c4+2] = tv.z; Ts[r][c4+3] = tv.w;
            Ws[r][c4+0] = wv.x; Ws[r][c4+1] = wv.y; Ws[r][c4+2] = wv.z; Ws[r][c4+3] = wv.w;
        }
        __syncthreads();
#pragma unroll 8
        for (int i = 0; i < 64; i++){
            float ta[4], wb_[4];
#pragma unroll
            for (int a = 0; a < 4; a++) ta[a]  = Ts[ti*4+a][i];
#pragma unroll
            for (int e = 0; e < 4; e++) wb_[e] = Ws[tj*4+e][i];
#pragma unroll
            for (int a = 0; a < 4; a++)
#pragma unroll
                for (int e = 0; e < 4; e++) acc[a][e] += ta[a] * wb_[e];
        }
        __syncthreads();
    }

    float* kvp = g_kv + (size_t)bh * 4096;
#pragma unroll
    for (int a = 0; a < 4; a++){
        const int d = ti*4 + a;
#pragma unroll
        for (int e4 = 0; e4 < 4; e4++){
            const int e = tj*4 + e4;
            float add = acc[a][e4];
            if (seg == 0){
                const float bkd = bk[h*64 + d];
                const float ud  = g_uv[0][b][h*64 + d];
                const float bve = bv[h*64 + e];
                const float we  = g_uv[1][b][h*64 + e];
                add += ud*bve + bkd*we + (float)SEQ*bkd*bve;
            }
            atomicAdd(&kvp[d*64 + e], add);
        }
    }
}

// ---------------- fold: xnorm(kv) @ Wo^T -> W2 (fp16), 16 j-slices ---------------
__global__ void __launch_bounds__(256) fold_kernel(
    const float* __restrict__ Wo, const float* __restrict__ gamma)
{
    const int bh = blockIdx.x, jc = blockIdx.y;
    const int b = bh >> 4, h = bh & 15;
    const int j0 = jc * 64;
    __shared__ float kvn[64][65];
    __shared__ float rn[64];
    const int tid = threadIdx.x;
    const float* kvsrc = g_kv + (size_t)bh * 4096;
    for (int l = tid; l < 4096; l += 256) kvn[l>>6][l&63] = kvsrc[l];
    __syncthreads();
    if (tid < 64){
        float s = 0.f;
#pragma unroll 16
        for (int d = 0; d < 64; d++){ float x = kvn[tid][d]; s += x*x; }
        rn[tid] = gamma[h] * rsqrtf(s);
    }
    __syncthreads();
    const int i = tid & 63, jg = tid >> 6;
    const float sc = rn[i];
    __half* w2 = g_w2 + (size_t)b*DM*DM;
    for (int j = jg; j < 64; j += 4){
        const float* wr = Wo + (size_t)(j0+j)*DM + h*64;
        float acc = 0.f;
#pragma unroll 16
        for (int d = 0; d < 64; d++) acc += kvn[i][d] * __ldg(wr + d);
        w2[(size_t)(j0+j)*DM + h*64 + i] = __float2half(acc * sc);
    }
}

// ---------------- launch ----------------------------------------------------------
extern "C" void kernel_launch(void* const* d_in, const int* in_sizes, int n_in,
                              void* d_out, int out_size)
{
    const float* queries = (const float*)d_in[0];
    const float* keys    = (const float*)d_in[1];
    const float* values  = (const float*)d_in[2];
    const float* Wq = (const float*)d_in[3];
    const float* bq = (const float*)d_in[4];
    const float* Wk = (const float*)d_in[5];
    const float* bk = (const float*)d_in[6];
    const float* Wv = (const float*)d_in[7];
    const float* bv = (const float*)d_in[8];
    const float* Wo = (const float*)d_in[9];
    const float* bo = (const float*)d_in[10];
    const float* gamma = (const float*)d_in[11];
    float* out = (float*)d_out;

    cudaFuncSetAttribute(combo_mma, cudaFuncAttributeMaxDynamicSharedMemorySize, DYN);
    cudaFuncSetAttribute(t_combo,   cudaFuncAttributeMaxDynamicSharedMemorySize, T_DYN);
    cudaFuncSetAttribute(out_mma,   cudaFuncAttributeMaxDynamicSharedMemorySize, DYN);

    conv_all<<<CONV_GRID, 256>>>(queries, keys, values, Wq, Wk);
    combo_mma<<<COMBO_GRID, NTHR, DYN>>>(bq, gamma);
    t_combo<<<TCOMBO_GRID, NTHR, T_DYN>>>(Wk, Wv);
    kv_small<<<dim3(BATCH*H, KV_SEG), 256>>>(Wv, bk, bv);
    fold_kernel<<<dim3(BATCH*H, 16), 256>>>(Wo, gamma);
    out_mma<<<dim3(DM/BN, SEQ/BM, BATCH), NTHR, DYN>>>(bo, out);
}